// round 3
// baseline (speedup 1.0000x reference)
#include <cuda_runtime.h>
#include <cuda_bf16.h>
#include <mma.h>
#include <cstdint>

using namespace nvcuda;

#define BATCH 8
#define SEQ   2048
#define DIM   1024

// ---------------- split helpers ----------------
__device__ __forceinline__ float tf32r(float x) {
    uint32_t u; asm("cvt.rna.tf32.f32 %0, %1;" : "=r"(u) : "f"(x));
    return __uint_as_float(u);
}
__device__ __forceinline__ void tf32_split(float v, float& h, float& m) {
    h = tf32r(v);
    m = tf32r(v - h);
}
__device__ __forceinline__ void bf16_split(float v, __nv_bfloat16& h, __nv_bfloat16& m) {
    h = __float2bfloat16_rn(v);
    m = __float2bfloat16_rn(v - __bfloat162float(h));
}

// ===========================================================================
// Scores: S = X X^T (lower-triangular tiles), TF32 x3 emulation via wmma.
// Block: 128x128 tile, 512 threads = 16 warps (4x4), warp tile 32x32.
// ===========================================================================
#define S_BK   16
#define S_LDA  20                   // padded row (floats)
#define S_PART (128 * S_LDA)        // 2560 floats
#define S_STG  (4 * S_PART)         // Ah|Am|Bh|Bm = 10240 floats
#define S_SMEM (2 * S_STG * 4)      // 81920 bytes

__global__ void __launch_bounds__(512, 1) score_tc(const float* __restrict__ x,
                                                   float* __restrict__ Sg) {
    const int b = blockIdx.z, it = blockIdx.y, jt = blockIdx.x;
    if (jt > it) return;

    extern __shared__ float sm[];
    const float* X = x + (size_t)b * SEQ * DIM;
    float* Sb = Sg + (size_t)b * SEQ * SEQ;
    const int i0 = it * 128, j0 = jt * 128;

    const int tid = threadIdx.x, wid = tid >> 5;
    const int wi = wid >> 2, wj = wid & 3;
    const int r = tid >> 2, cg = (tid & 3) << 2;

    wmma::fragment<wmma::accumulator, 16, 16, 8, float> acc[2][2];
#pragma unroll
    for (int i = 0; i < 2; i++)
#pragma unroll
        for (int j = 0; j < 2; j++) wmma::fill_fragment(acc[i][j], 0.0f);

    float4 va, vb;

    // prologue: chunk 0
    {
        const int k0 = 0;
        va = *(const float4*)&X[(size_t)(i0 + r) * DIM + k0 + cg];
        vb = *(const float4*)&X[(size_t)(j0 + r) * DIM + k0 + cg];
        float* Ah = sm;          float* Am = Ah + S_PART;
        float* Bh = Am + S_PART; float* Bm = Bh + S_PART;
        float h0, m0, h1, m1, h2, m2, h3, m3;
        tf32_split(va.x, h0, m0); tf32_split(va.y, h1, m1);
        tf32_split(va.z, h2, m2); tf32_split(va.w, h3, m3);
        Ah[r * S_LDA + cg + 0] = h0; Ah[r * S_LDA + cg + 1] = h1;
        Ah[r * S_LDA + cg + 2] = h2; Ah[r * S_LDA + cg + 3] = h3;
        Am[r * S_LDA + cg + 0] = m0; Am[r * S_LDA + cg + 1] = m1;
        Am[r * S_LDA + cg + 2] = m2; Am[r * S_LDA + cg + 3] = m3;
        tf32_split(vb.x, h0, m0); tf32_split(vb.y, h1, m1);
        tf32_split(vb.z, h2, m2); tf32_split(vb.w, h3, m3);
        Bh[r * S_LDA + cg + 0] = h0; Bh[r * S_LDA + cg + 1] = h1;
        Bh[r * S_LDA + cg + 2] = h2; Bh[r * S_LDA + cg + 3] = h3;
        Bm[r * S_LDA + cg + 0] = m0; Bm[r * S_LDA + cg + 1] = m1;
        Bm[r * S_LDA + cg + 2] = m2; Bm[r * S_LDA + cg + 3] = m3;
    }
    __syncthreads();

    const int NC = DIM / S_BK;   // 64
    for (int c = 0; c < NC; c++) {
        if (c + 1 < NC) {
            const int k0 = (c + 1) * S_BK;
            va = *(const float4*)&X[(size_t)(i0 + r) * DIM + k0 + cg];
            vb = *(const float4*)&X[(size_t)(j0 + r) * DIM + k0 + cg];
        }
        const int s = c & 1;
        const float* Ah = sm + s * S_STG;
        const float* Am = Ah + S_PART;
        const float* Bh = Am + S_PART;
        const float* Bm = Bh + S_PART;
#pragma unroll
        for (int kf = 0; kf < 2; kf++) {
            wmma::fragment<wmma::matrix_a, 16, 16, 8, wmma::precision::tf32, wmma::row_major> ah[2], am[2];
            wmma::fragment<wmma::matrix_b, 16, 16, 8, wmma::precision::tf32, wmma::col_major> bh[2], bm[2];
#pragma unroll
            for (int i = 0; i < 2; i++) {
                wmma::load_matrix_sync(ah[i], Ah + (wi * 32 + i * 16) * S_LDA + kf * 8, S_LDA);
                wmma::load_matrix_sync(am[i], Am + (wi * 32 + i * 16) * S_LDA + kf * 8, S_LDA);
            }
#pragma unroll
            for (int j = 0; j < 2; j++) {
                wmma::load_matrix_sync(bh[j], Bh + (wj * 32 + j * 16) * S_LDA + kf * 8, S_LDA);
                wmma::load_matrix_sync(bm[j], Bm + (wj * 32 + j * 16) * S_LDA + kf * 8, S_LDA);
            }
#pragma unroll
            for (int i = 0; i < 2; i++)
#pragma unroll
                for (int j = 0; j < 2; j++) {
                    wmma::mma_sync(acc[i][j], ah[i], bh[j], acc[i][j]);
                    wmma::mma_sync(acc[i][j], ah[i], bm[j], acc[i][j]);
                    wmma::mma_sync(acc[i][j], am[i], bh[j], acc[i][j]);
                }
        }
        if (c + 1 < NC) {
            float* Ah2 = sm + ((c + 1) & 1) * S_STG;
            float* Am2 = Ah2 + S_PART;
            float* Bh2 = Am2 + S_PART;
            float* Bm2 = Bh2 + S_PART;
            float h0, m0, h1, m1, h2, m2, h3, m3;
            tf32_split(va.x, h0, m0); tf32_split(va.y, h1, m1);
            tf32_split(va.z, h2, m2); tf32_split(va.w, h3, m3);
            Ah2[r * S_LDA + cg + 0] = h0; Ah2[r * S_LDA + cg + 1] = h1;
            Ah2[r * S_LDA + cg + 2] = h2; Ah2[r * S_LDA + cg + 3] = h3;
            Am2[r * S_LDA + cg + 0] = m0; Am2[r * S_LDA + cg + 1] = m1;
            Am2[r * S_LDA + cg + 2] = m2; Am2[r * S_LDA + cg + 3] = m3;
            tf32_split(vb.x, h0, m0); tf32_split(vb.y, h1, m1);
            tf32_split(vb.z, h2, m2); tf32_split(vb.w, h3, m3);
            Bh2[r * S_LDA + cg + 0] = h0; Bh2[r * S_LDA + cg + 1] = h1;
            Bh2[r * S_LDA + cg + 2] = h2; Bh2[r * S_LDA + cg + 3] = h3;
            Bm2[r * S_LDA + cg + 0] = m0; Bm2[r * S_LDA + cg + 1] = m1;
            Bm2[r * S_LDA + cg + 2] = m2; Bm2[r * S_LDA + cg + 3] = m3;
        }
        __syncthreads();
    }

#pragma unroll
    for (int i = 0; i < 2; i++)
#pragma unroll
        for (int j = 0; j < 2; j++)
            wmma::store_matrix_sync(&Sb[(size_t)(i0 + wi * 32 + i * 16) * SEQ + j0 + wj * 32 + j * 16],
                                    acc[i][j], SEQ, wmma::mem_row_major);
}

// ===========================================================================
// Softmax rows (strict-lower causal; row0 uniform 1/T).
// ===========================================================================
__global__ __launch_bounds__(256) void softmax_rows(float* __restrict__ Wg) {
    const int i = blockIdx.x, b = blockIdx.y;
    float* row = Wg + ((size_t)b * SEQ + i) * SEQ;
    const int tid = threadIdx.x;
    if (i == 0) {
        const float v = 1.0f / (float)SEQ;
#pragma unroll
        for (int s = 0; s < 8; s++) row[tid + s * 256] = v;
        return;
    }
    float vals[8];
    float m = -3.0e38f;
#pragma unroll
    for (int s = 0; s < 8; s++) {
        int j = tid + s * 256;
        float v = (j < i) ? row[j] : -3.0e38f;
        vals[s] = v;
        m = fmaxf(m, v);
    }
    __shared__ float sred[8];
#pragma unroll
    for (int o = 16; o; o >>= 1) m = fmaxf(m, __shfl_xor_sync(0xffffffffu, m, o));
    if ((tid & 31) == 0) sred[tid >> 5] = m;
    __syncthreads();
    m = sred[0];
#pragma unroll
    for (int w = 1; w < 8; w++) m = fmaxf(m, sred[w]);
    float l = 0.f;
#pragma unroll
    for (int s = 0; s < 8; s++) {
        int j = tid + s * 256;
        float e = (j < i) ? __expf(vals[s] - m) : 0.f;
        vals[s] = e;
        l += e;
    }
#pragma unroll
    for (int o = 16; o; o >>= 1) l += __shfl_xor_sync(0xffffffffu, l, o);
    __syncthreads();
    if ((tid & 31) == 0) sred[tid >> 5] = l;
    __syncthreads();
    l = 0.f;
#pragma unroll
    for (int w = 0; w < 8; w++) l += sred[w];
    const float inv = 1.0f / l;
#pragma unroll
    for (int s = 0; s < 8; s++) row[tid + s * 256] = vals[s] * inv;
}

// ===========================================================================
// AV: O = W @ X, K bounded at (it+1)*128, BF16 x3 emulation via wmma.
// ===========================================================================
#define A_BK    32
#define A_LDA   40                      // bf16 elems per A row
#define A_LDB   136                     // bf16 elems per B row
#define A_APART (128 * A_LDA)           // 5120
#define A_BPART (32 * A_LDB)            // 4352
#define A_STG   (2 * A_APART + 2 * A_BPART)   // 18944 elems
#define A_SMEM  (2 * A_STG * 2)               // 75776 bytes

__global__ void __launch_bounds__(512, 1) av_tc(const float* __restrict__ Wg,
                                                const float* __restrict__ x,
                                                float* __restrict__ Og) {
    const int b = blockIdx.z, it = blockIdx.y, dt = blockIdx.x;

    extern __shared__ __nv_bfloat16 smb[];
    const float* W = Wg + (size_t)b * SEQ * SEQ;
    const float* X = x + (size_t)b * SEQ * DIM;
    float* Ob = Og + (size_t)b * SEQ * DIM;
    const int i0 = it * 128, d0 = dt * 128;

    const int tid = threadIdx.x, wid = tid >> 5;
    const int wi = wid >> 2, wj = wid & 3;
    // A mapping: 2 float4/thread over 128x32; B mapping: 2 float4/thread over 32x128
    const int ra0 = tid >> 3, ca0 = (tid & 7) << 2;
    const int kb0 = tid >> 5, cb0 = (tid & 31) << 2;

    wmma::fragment<wmma::accumulator, 16, 16, 16, float> acc[2][2];
#pragma unroll
    for (int i = 0; i < 2; i++)
#pragma unroll
        for (int j = 0; j < 2; j++) wmma::fill_fragment(acc[i][j], 0.0f);

    float4 wa[2], xb[2];

    auto fill = [&](int s) {
        __nv_bfloat16* Ah = smb + s * A_STG;
        __nv_bfloat16* Am = Ah + A_APART;
        __nv_bfloat16* Bh = Am + A_APART;
        __nv_bfloat16* Bm = Bh + A_BPART;
#pragma unroll
        for (int q = 0; q < 2; q++) {
            const int ra = ra0 + q * 64;     // (tid + q*512) >> 3
            float vv[4] = {wa[q].x, wa[q].y, wa[q].z, wa[q].w};
#pragma unroll
            for (int e = 0; e < 4; e++) {
                __nv_bfloat16 h, m;
                bf16_split(vv[e], h, m);
                Ah[ra * A_LDA + ca0 + e] = h;
                Am[ra * A_LDA + ca0 + e] = m;
            }
            const int kb = kb0 + q * 16;
            float uu[4] = {xb[q].x, xb[q].y, xb[q].z, xb[q].w};
#pragma unroll
            for (int e = 0; e < 4; e++) {
                __nv_bfloat16 h, m;
                bf16_split(uu[e], h, m);
                Bh[kb * A_LDB + cb0 + e] = h;
                Bm[kb * A_LDB + cb0 + e] = m;
            }
        }
    };
    auto gload = [&](int c) {
        const int k0 = c * A_BK;
#pragma unroll
        for (int q = 0; q < 2; q++) {
            wa[q] = *(const float4*)&W[(size_t)(i0 + ra0 + q * 64) * SEQ + k0 + ca0];
            xb[q] = *(const float4*)&X[(size_t)(k0 + kb0 + q * 16) * DIM + d0 + cb0];
        }
    };

    const int NC = (it + 1) * (128 / A_BK);   // causal K bound
    gload(0);
    fill(0);
    __syncthreads();

    for (int c = 0; c < NC; c++) {
        if (c + 1 < NC) gload(c + 1);
        const int s = c & 1;
        const __nv_bfloat16* Ah = smb + s * A_STG;
        const __nv_bfloat16* Am = Ah + A_APART;
        const __nv_bfloat16* Bh = Am + A_APART;
        const __nv_bfloat16* Bm = Bh + A_BPART;
#pragma unroll
        for (int kf = 0; kf < 2; kf++) {
            wmma::fragment<wmma::matrix_a, 16, 16, 16, __nv_bfloat16, wmma::row_major> ah[2], am[2];
            wmma::fragment<wmma::matrix_b, 16, 16, 16, __nv_bfloat16, wmma::row_major> bh[2], bm[2];
#pragma unroll
            for (int i = 0; i < 2; i++) {
                wmma::load_matrix_sync(ah[i], Ah + (wi * 32 + i * 16) * A_LDA + kf * 16, A_LDA);
                wmma::load_matrix_sync(am[i], Am + (wi * 32 + i * 16) * A_LDA + kf * 16, A_LDA);
            }
#pragma unroll
            for (int j = 0; j < 2; j++) {
                wmma::load_matrix_sync(bh[j], Bh + (kf * 16) * A_LDB + wj * 32 + j * 16, A_LDB);
                wmma::load_matrix_sync(bm[j], Bm + (kf * 16) * A_LDB + wj * 32 + j * 16, A_LDB);
            }
#pragma unroll
            for (int i = 0; i < 2; i++)
#pragma unroll
                for (int j = 0; j < 2; j++) {
                    wmma::mma_sync(acc[i][j], ah[i], bh[j], acc[i][j]);
                    wmma::mma_sync(acc[i][j], ah[i], bm[j], acc[i][j]);
                    wmma::mma_sync(acc[i][j], am[i], bh[j], acc[i][j]);
                }
        }
        if (c + 1 < NC) fill((c + 1) & 1);
        __syncthreads();
    }

#pragma unroll
    for (int i = 0; i < 2; i++)
#pragma unroll
        for (int j = 0; j < 2; j++)
            wmma::store_matrix_sync(&Ob[(size_t)(i0 + wi * 32 + i * 16) * DIM + d0 + wj * 32 + j * 16],
                                    acc[i][j], DIM, wmma::mem_row_major);
}

// ===========================================================================
// Row 0: att_vec[b,0,:] = mean_j x[b,j,:]  (two-stage)
// ===========================================================================
__device__ float g_r0part[BATCH][16][DIM];

__global__ __launch_bounds__(256) void r0_partial(const float* __restrict__ x) {
    const int b = blockIdx.y, sl = blockIdx.x;
    const float* X = x + (size_t)b * SEQ * DIM;
    const int tid = threadIdx.x;
    float s[4] = {0.f, 0.f, 0.f, 0.f};
    const int j0 = sl * 128;
    for (int j = j0; j < j0 + 128; j++) {
#pragma unroll
        for (int q = 0; q < 4; q++) s[q] += X[(size_t)j * DIM + tid + q * 256];
    }
#pragma unroll
    for (int q = 0; q < 4; q++) g_r0part[b][sl][tid + q * 256] = s[q];
}

__global__ __launch_bounds__(256) void r0_reduce(float* __restrict__ Og) {
    const int b = blockIdx.y;
    const int d = blockIdx.x * 256 + threadIdx.x;
    float s = 0.f;
#pragma unroll
    for (int sl = 0; sl < 16; sl++) s += g_r0part[b][sl][d];
    Og[(size_t)b * SEQ * DIM + d] = s * (1.0f / (float)SEQ);
}

// ===========================================================================
extern "C" void kernel_launch(void* const* d_in, const int* in_sizes, int n_in,
                              void* d_out, int out_size) {
    const float* x = (const float*)d_in[0];
    float* out     = (float*)d_out;
    float* att_vec = out;                                   // [B,T,D]
    float* Wg      = out + (size_t)BATCH * SEQ * DIM;       // [B,T,T]

    cudaFuncSetAttribute(score_tc, cudaFuncAttributeMaxDynamicSharedMemorySize, S_SMEM);
    cudaFuncSetAttribute(av_tc, cudaFuncAttributeMaxDynamicSharedMemorySize, A_SMEM);

    dim3 g1(SEQ / 128, SEQ / 128, BATCH);
    score_tc<<<g1, 512, S_SMEM>>>(x, Wg);

    dim3 g2(SEQ, BATCH);
    softmax_rows<<<g2, 256>>>(Wg);

    dim3 g3(DIM / 128, SEQ / 128, BATCH);
    av_tc<<<g3, 512, A_SMEM>>>(Wg, x, att_vec);

    dim3 g4(16, BATCH);
    r0_partial<<<g4, 256>>>(x);
    dim3 g5(DIM / 256, BATCH);
    r0_reduce<<<g5, 256>>>(att_vec);
}

// round 5
// speedup vs baseline: 1.4258x; 1.4258x over previous
#include <cuda_runtime.h>
#include <cstdint>

#define BATCH 8
#define SEQ   2048
#define DIM   1024

#define BM 128
#define BN 128
#define BK 16
#define TPB 256
#define LDR 132   // smem row stride (floats): 128 + 4 pad, 16B-aligned rows

typedef unsigned long long ull;

__device__ __forceinline__ void ffma2(ull& d, ull a, ull b) {
    asm("fma.rn.f32x2 %0, %1, %2, %0;" : "+l"(d) : "l"(a), "l"(b));
}
__device__ __forceinline__ ull dup2(float v) {
    ull r; asm("mov.b64 %0, {%1, %2};" : "=l"(r) : "f"(v), "f"(v)); return r;
}
__device__ __forceinline__ void unpk(ull p, float& lo, float& hi) {
    asm("mov.b64 {%0, %1}, %2;" : "=f"(lo), "=f"(hi) : "l"(p));
}

// ---------------------------------------------------------------------------
// Core compute: 128x128 tile, 256 threads, 8x8 per thread via f32x2 pairs.
// acc2[v][p]: v = 8 b-columns, p = 4 m-pairs (rows 2p,2p+1 of the 8).
// ---------------------------------------------------------------------------
struct Acc {
    ull a[8][4];
};

__device__ __forceinline__ void compute_chunk(const float (*As)[LDR],
                                              const float (*Bs)[LDR],
                                              int tm, int tn, Acc& acc) {
#pragma unroll
    for (int k = 0; k < BK; k++) {
        ulonglong2 a01 = *(const ulonglong2*)&As[k][tm * 4];
        ulonglong2 a23 = *(const ulonglong2*)&As[k][64 + tm * 4];
        float4 b0 = *(const float4*)&Bs[k][tn * 4];
        float4 b1 = *(const float4*)&Bs[k][64 + tn * 4];
        ull ap[4] = {a01.x, a01.y, a23.x, a23.y};
        ull bd[8] = {dup2(b0.x), dup2(b0.y), dup2(b0.z), dup2(b0.w),
                     dup2(b1.x), dup2(b1.y), dup2(b1.z), dup2(b1.w)};
#pragma unroll
        for (int v = 0; v < 8; v++)
#pragma unroll
            for (int p = 0; p < 4; p++) ffma2(acc.a[v][p], ap[p], bd[v]);
    }
}

__device__ __forceinline__ void store_tile(float* dst, size_t ld, int tm, int tn,
                                           const Acc& acc) {
#pragma unroll
    for (int u = 0; u < 8; u++) {
        const int p = u >> 1, hi = u & 1;
        const int r = (u < 4) ? (tm * 4 + u) : (64 + tm * 4 + (u - 4));
        // remap: rows covered are tm*4+0..3 (pairs p=0,1) and 64+tm*4+0..3 (p=2,3)
        float c[8];
#pragma unroll
        for (int v = 0; v < 8; v++) {
            float lo, hh;
            unpk(acc.a[v][p], lo, hh);
            c[v] = hi ? hh : lo;
        }
        *(float4*)&dst[(size_t)r * ld + tn * 4]      = make_float4(c[0], c[1], c[2], c[3]);
        *(float4*)&dst[(size_t)r * ld + 64 + tn * 4] = make_float4(c[4], c[5], c[6], c[7]);
    }
}

// ---------------------------------------------------------------------------
// Kernel 1: scores S = X X^T, lower-triangular tiles.
// ---------------------------------------------------------------------------
__global__ __launch_bounds__(TPB, 2) void gemm_scores(const float* __restrict__ x,
                                                      float* __restrict__ Sg) {
    const int b = blockIdx.z, it = blockIdx.y, jt = blockIdx.x;
    if (jt > it) return;

    const float* X = x + (size_t)b * SEQ * DIM;
    float* Sb = Sg + (size_t)b * SEQ * SEQ;

    __shared__ float As[2][BK][LDR];
    __shared__ float Bs[2][BK][LDR];

    const int tid = threadIdx.x;
    const int tm = tid / 16, tn = tid % 16;
    const int i0 = it * BM, j0 = jt * BN;
    const int lr = tid / 4, lc = (tid % 4) * 4;

    Acc acc;
#pragma unroll
    for (int v = 0; v < 8; v++)
#pragma unroll
        for (int p = 0; p < 4; p++) acc.a[v][p] = 0ull;

    float4 a0, a1, b0, b1;
    auto ldg = [&](int k0) {
        a0 = *(const float4*)&X[(size_t)(i0 + lr)      * DIM + k0 + lc];
        a1 = *(const float4*)&X[(size_t)(i0 + lr + 64) * DIM + k0 + lc];
        b0 = *(const float4*)&X[(size_t)(j0 + lr)      * DIM + k0 + lc];
        b1 = *(const float4*)&X[(size_t)(j0 + lr + 64) * DIM + k0 + lc];
    };
    auto sts = [&](int s) {
        As[s][lc + 0][lr] = a0.x; As[s][lc + 1][lr] = a0.y;
        As[s][lc + 2][lr] = a0.z; As[s][lc + 3][lr] = a0.w;
        As[s][lc + 0][lr + 64] = a1.x; As[s][lc + 1][lr + 64] = a1.y;
        As[s][lc + 2][lr + 64] = a1.z; As[s][lc + 3][lr + 64] = a1.w;
        Bs[s][lc + 0][lr] = b0.x; Bs[s][lc + 1][lr] = b0.y;
        Bs[s][lc + 2][lr] = b0.z; Bs[s][lc + 3][lr] = b0.w;
        Bs[s][lc + 0][lr + 64] = b1.x; Bs[s][lc + 1][lr + 64] = b1.y;
        Bs[s][lc + 2][lr + 64] = b1.z; Bs[s][lc + 3][lr + 64] = b1.w;
    };

    const int NC = DIM / BK;
    ldg(0);
    sts(0);
    __syncthreads();
    for (int c = 0; c < NC; c++) {
        if (c + 1 < NC) ldg((c + 1) * BK);
        compute_chunk(As[c & 1], Bs[c & 1], tm, tn, acc);
        if (c + 1 < NC) sts((c + 1) & 1);
        __syncthreads();
    }
    store_tile(&Sb[(size_t)i0 * SEQ + j0], SEQ, tm, tn, acc);
}

// ---------------------------------------------------------------------------
// Kernel 2: softmax rows (strict-lower causal; row0 uniform 1/T).
// ---------------------------------------------------------------------------
__global__ __launch_bounds__(256) void softmax_rows(float* __restrict__ Wg) {
    const int i = blockIdx.x, b = blockIdx.y;
    float* row = Wg + ((size_t)b * SEQ + i) * SEQ;
    const int tid = threadIdx.x;
    if (i == 0) {
        const float v = 1.0f / (float)SEQ;
#pragma unroll
        for (int s = 0; s < 8; s++) row[tid + s * 256] = v;
        return;
    }
    float vals[8];
    float m = -3.0e38f;
#pragma unroll
    for (int s = 0; s < 8; s++) {
        int j = tid + s * 256;
        float v = (j < i) ? row[j] : -3.0e38f;
        vals[s] = v;
        m = fmaxf(m, v);
    }
    __shared__ float sred[8];
#pragma unroll
    for (int o = 16; o; o >>= 1) m = fmaxf(m, __shfl_xor_sync(0xffffffffu, m, o));
    if ((tid & 31) == 0) sred[tid >> 5] = m;
    __syncthreads();
    m = sred[0];
#pragma unroll
    for (int w = 1; w < 8; w++) m = fmaxf(m, sred[w]);
    float l = 0.f;
#pragma unroll
    for (int s = 0; s < 8; s++) {
        int j = tid + s * 256;
        float e = (j < i) ? __expf(vals[s] - m) : 0.f;
        vals[s] = e;
        l += e;
    }
#pragma unroll
    for (int o = 16; o; o >>= 1) l += __shfl_xor_sync(0xffffffffu, l, o);
    __syncthreads();
    if ((tid & 31) == 0) sred[tid >> 5] = l;
    __syncthreads();
    l = 0.f;
#pragma unroll
    for (int w = 0; w < 8; w++) l += sred[w];
    const float inv = 1.0f / l;
#pragma unroll
    for (int s = 0; s < 8; s++) row[tid + s * 256] = vals[s] * inv;
}

// ---------------------------------------------------------------------------
// Kernel 3: O = W @ X, K bounded at (it+1)*BM (rows>0; row 0 fixed later).
// ---------------------------------------------------------------------------
__global__ __launch_bounds__(TPB, 2) void gemm_av(const float* __restrict__ Wg,
                                                  const float* __restrict__ x,
                                                  float* __restrict__ Og) {
    const int b = blockIdx.z, it = blockIdx.y, dt = blockIdx.x;

    const float* W = Wg + (size_t)b * SEQ * SEQ;
    const float* X = x + (size_t)b * SEQ * DIM;
    float* Ob = Og + (size_t)b * SEQ * DIM;

    __shared__ float As[2][BK][LDR];
    __shared__ float Bs[2][BK][LDR];

    const int tid = threadIdx.x;
    const int tm = tid / 16, tn = tid % 16;
    const int i0 = it * BM, d0 = dt * BN;

    const int lrA = tid / 4, lcA = (tid % 4) * 4;
    const int lrB = tid / 32, lcB = (tid % 32) * 4;

    Acc acc;
#pragma unroll
    for (int v = 0; v < 8; v++)
#pragma unroll
        for (int p = 0; p < 4; p++) acc.a[v][p] = 0ull;

    float4 a0, a1, b0, b1;
    auto ldg = [&](int k0) {
        a0 = *(const float4*)&W[(size_t)(i0 + lrA)      * SEQ + k0 + lcA];
        a1 = *(const float4*)&W[(size_t)(i0 + lrA + 64) * SEQ + k0 + lcA];
        b0 = *(const float4*)&X[(size_t)(k0 + lrB)     * DIM + d0 + lcB];
        b1 = *(const float4*)&X[(size_t)(k0 + lrB + 8) * DIM + d0 + lcB];
    };
    auto sts = [&](int s) {
        As[s][lcA + 0][lrA] = a0.x; As[s][lcA + 1][lrA] = a0.y;
        As[s][lcA + 2][lrA] = a0.z; As[s][lcA + 3][lrA] = a0.w;
        As[s][lcA + 0][lrA + 64] = a1.x; As[s][lcA + 1][lrA + 64] = a1.y;
        As[s][lcA + 2][lrA + 64] = a1.z; As[s][lcA + 3][lrA + 64] = a1.w;
        *(float4*)&Bs[s][lrB][lcB]     = b0;
        *(float4*)&Bs[s][lrB + 8][lcB] = b1;
    };

    const int NC = (it + 1) * (BM / BK);   // causal K bound
    ldg(0);
    sts(0);
    __syncthreads();
    for (int c = 0; c < NC; c++) {
        if (c + 1 < NC) ldg((c + 1) * BK);
        compute_chunk(As[c & 1], Bs[c & 1], tm, tn, acc);
        if (c + 1 < NC) sts((c + 1) & 1);
        __syncthreads();
    }
    store_tile(&Ob[(size_t)i0 * DIM + d0], DIM, tm, tn, acc);
}

// ---------------------------------------------------------------------------
// Row 0: att_vec[b,0,:] = mean_j x[b,j,:]  (two-stage, 64 slices/batch)
// ---------------------------------------------------------------------------
__device__ float g_r0part[BATCH][64][DIM];

__global__ __launch_bounds__(256) void r0_partial(const float* __restrict__ x) {
    const int b = blockIdx.y, sl = blockIdx.x;
    const float* X = x + (size_t)b * SEQ * DIM;
    const int tid = threadIdx.x;
    float s[4] = {0.f, 0.f, 0.f, 0.f};
    const int j0 = sl * 32;
    for (int j = j0; j < j0 + 32; j++) {
#pragma unroll
        for (int q = 0; q < 4; q++) s[q] += X[(size_t)j * DIM + tid + q * 256];
    }
#pragma unroll
    for (int q = 0; q < 4; q++) g_r0part[b][sl][tid + q * 256] = s[q];
}

__global__ __launch_bounds__(256) void r0_reduce(float* __restrict__ Og) {
    const int b = blockIdx.y;
    const int d = blockIdx.x * 256 + threadIdx.x;
    float s = 0.f;
#pragma unroll
    for (int sl = 0; sl < 64; sl++) s += g_r0part[b][sl][d];
    Og[(size_t)b * SEQ * DIM + d] = s * (1.0f / (float)SEQ);
}

// ---------------------------------------------------------------------------
extern "C" void kernel_launch(void* const* d_in, const int* in_sizes, int n_in,
                              void* d_out, int out_size) {
    const float* x = (const float*)d_in[0];
    float* out     = (float*)d_out;
    float* att_vec = out;                                   // [B,T,D]
    float* Wg      = out + (size_t)BATCH * SEQ * DIM;       // [B,T,T]

    dim3 g1(SEQ / BN, SEQ / BM, BATCH);
    gemm_scores<<<g1, TPB>>>(x, Wg);

    dim3 g2(SEQ, BATCH);
    softmax_rows<<<g2, 256>>>(Wg);

    dim3 g3(DIM / BN, SEQ / BM, BATCH);
    gemm_av<<<g3, TPB>>>(Wg, x, att_vec);

    dim3 g4(64, BATCH);
    r0_partial<<<g4, 256>>>(x);
    dim3 g5(DIM / 256, BATCH);
    r0_reduce<<<g5, 256>>>(att_vec);
}